// round 1
// baseline (speedup 1.0000x reference)
#include <cuda_runtime.h>

// Folded affine map: u[k] = Weff[k]·z_row + beff[k], k=0..3 (u[4] unused)
__device__ float g_Weff[24];
__device__ float g_beff[4];

#define ALPHA1 1.2566f
#define ALPHA2 1.5f
#define ALPHA3 0.9f
#define S_STAR 20.0f
#define TAU    4.0f

// ---------------------------------------------------------------------------
// Prelude: fold W3@W2@W1 (rows 0..3) and beff = W3@(W2@b1+b2)+b3.
// One block, runs every launch (deterministic).
// ---------------------------------------------------------------------------
__global__ void fold_weights_kernel(const float* __restrict__ W1,
                                    const float* __restrict__ b1,
                                    const float* __restrict__ W2,
                                    const float* __restrict__ b2,
                                    const float* __restrict__ W3,
                                    const float* __restrict__ b3) {
    __shared__ float T[5 * 50];     // W3 @ W2
    __shared__ float w2b1[100];     // W2 @ b1
    const int t = threadIdx.x;

    // T[k][c] = sum_j W3[k][j] * W2[j][c]
    for (int idx = t; idx < 5 * 50; idx += blockDim.x) {
        const int k = idx / 50, c = idx % 50;
        float s = 0.f;
        #pragma unroll 4
        for (int j = 0; j < 100; ++j) s = fmaf(W3[k * 100 + j], W2[j * 50 + c], s);
        T[idx] = s;
    }
    // w2b1[j] = sum_c W2[j][c] * b1[c]
    for (int j = t; j < 100; j += blockDim.x) {
        float s = 0.f;
        #pragma unroll 5
        for (int c = 0; c < 50; ++c) s = fmaf(W2[j * 50 + c], b1[c], s);
        w2b1[j] = s;
    }
    __syncthreads();

    // Weff[k][i] = sum_c T[k][c] * W1[c][i]   (only k=0..3 needed)
    if (t < 24) {
        const int k = t / 6, i = t % 6;
        float s = 0.f;
        #pragma unroll 5
        for (int c = 0; c < 50; ++c) s = fmaf(T[k * 50 + c], W1[c * 6 + i], s);
        g_Weff[t] = s;
    }
    // beff[k] = b3[k] + sum_j W3[k][j] * (w2b1[j] + b2[j])
    if (t >= 32 && t < 36) {
        const int k = t - 32;
        float s = b3[k];
        #pragma unroll 4
        for (int j = 0; j < 100; ++j) s = fmaf(W3[k * 100 + j], w2b1[j] + b2[j], s);
        g_beff[k] = s;
    }
}

// ---------------------------------------------------------------------------
// Main kernel: 4 outputs per thread, all loads/stores vectorized as float4.
// Per thread: 6 float4 row loads (z[24t..24t+23]) + 6 float4 column loads
// (z.flat[i*B + 4t]) + 1 float4 store. Pure streaming, HBM-bound.
// ---------------------------------------------------------------------------
__global__ __launch_bounds__(256) void barrier_main_kernel(
    const float* __restrict__ z, float* __restrict__ out, int nv /* = B/4 */) {
    const int t = blockIdx.x * blockDim.x + threadIdx.x;
    if (t >= nv) return;

    const float4* __restrict__ z4 = reinterpret_cast<const float4*>(z);

    // Folded affine parameters (L1/L2-resident, uniform across warp)
    float W[24], bf[4];
    #pragma unroll
    for (int i = 0; i < 24; ++i) W[i] = g_Weff[i];
    #pragma unroll
    for (int i = 0; i < 4; ++i) bf[i] = g_beff[i];

    // Row data: z rows 4t..4t+3 = 24 contiguous floats
    float rf[24];
    #pragma unroll
    for (int k = 0; k < 6; ++k) {
        float4 v = z4[6 * t + k];
        rf[4 * k + 0] = v.x; rf[4 * k + 1] = v.y;
        rf[4 * k + 2] = v.z; rf[4 * k + 3] = v.w;
    }

    // Column data: X[i][4t..4t+3] = z.flat[i*B + 4t ...]
    float4 c[6];
    #pragma unroll
    for (int i = 0; i < 6; ++i) c[i] = z4[(size_t)i * nv + t];
    float xc[6][4];
    #pragma unroll
    for (int i = 0; i < 6; ++i) {
        xc[i][0] = c[i].x; xc[i][1] = c[i].y; xc[i][2] = c[i].z; xc[i][3] = c[i].w;
    }

    // Constant d3u = d3 @ f  (index 0 is 0)
    const float d3u1 = TAU * ALPHA3;
    const float d3u2 = TAU * ALPHA1;
    const float d3u3 = 1.f - TAU * (ALPHA2 + ALPHA3);
    const float d3u4 = -TAU * ALPHA1;
    const float d3u5 = TAU * ALPHA2 - 1.f;
    // A = [-TAU, -TAU*ALPHA3], both negative -> ub = +1e30, lb = max(h/A)
    const float invA0 = -1.f / TAU;
    const float invA1 = -1.f / (TAU * ALPHA3);

    float res[4];
    #pragma unroll
    for (int l = 0; l < 4; ++l) {
        // Affine "MLP": u0..u3
        float u0 = bf[0], u1 = bf[1], u2 = bf[2], u3 = bf[3];
        #pragma unroll
        for (int i = 0; i < 6; ++i) {
            const float zi = rf[6 * l + i];
            u0 = fmaf(W[i],      zi, u0);
            u1 = fmaf(W[6 + i],  zi, u1);
            u2 = fmaf(W[12 + i], zi, u2);
            u3 = fmaf(W[18 + i], zi, u3);
        }

        const float x1 = xc[1][l], x2 = xc[2][l], x3 = xc[3][l];
        const float x4 = xc[4][l], x5 = xc[5][l];

        // fX rows (rows 0,1 of f are zero)
        const float fX2 = x1 - x3;
        const float fX3 = ALPHA3 * x1 + ALPHA1 * x2 - ALPHA2 * x3;
        const float fX4 = x3 - x5;
        const float fX5 = ALPHA3 * x3 + ALPHA1 * x4 - ALPHA2 * x5;

        const float eta1 = x2 + S_STAR - TAU * (x3 - x1);
        const float bb1  = fX2 - TAU * fX3 + u1 * eta1;

        const float eta2a = x4 + S_STAR - TAU * (x5 - x3);
        const float eta2b = d3u1 * x1 + d3u2 * x2 + d3u3 * x3 + d3u4 * x4 + d3u5 * x5;
        const float bb2   = d3u2 * fX2 + d3u3 * fX3 + d3u4 * fX4 + d3u5 * fX5
                          + u2 * eta2a + u3 * eta2b;

        const float lb = fmaxf(bb1 * invA0, bb2 * invA1);
        res[l] = fminf(fmaxf(2.f * u0, lb), 1e30f);
    }

    reinterpret_cast<float4*>(out)[t] =
        make_float4(res[0], res[1], res[2], res[3]);
}

// ---------------------------------------------------------------------------
// Inputs (metadata order): z, tilde_vh, W1, b1, W2, b2, W3, b3
// ---------------------------------------------------------------------------
extern "C" void kernel_launch(void* const* d_in, const int* in_sizes, int n_in,
                              void* d_out, int out_size) {
    const float* z  = (const float*)d_in[0];
    const float* W1 = (const float*)d_in[2];
    const float* b1 = (const float*)d_in[3];
    const float* W2 = (const float*)d_in[4];
    const float* b2 = (const float*)d_in[5];
    const float* W3 = (const float*)d_in[6];
    const float* b3 = (const float*)d_in[7];
    float* out = (float*)d_out;

    const int B  = in_sizes[0] / 6;   // 1048576
    const int nv = B / 4;             // 262144 float4 lanes

    fold_weights_kernel<<<1, 256>>>(W1, b1, W2, b2, W3, b3);

    const int threads = 256;
    const int blocks  = (nv + threads - 1) / threads;
    barrier_main_kernel<<<blocks, threads>>>(z, out, nv);
}

// round 2
// speedup vs baseline: 1.3885x; 1.3885x over previous
#include <cuda_runtime.h>

// Folded affine map: u[k] = Weff[k]·z_row + beff[k], k=0..3
__device__ float g_Weff[24];
__device__ float g_beff[4];

#define ALPHA1 1.2566f
#define ALPHA2 1.5f
#define ALPHA3 0.9f
#define S_STAR 20.0f
#define TAU    4.0f

// ---------------------------------------------------------------------------
// Prelude: fold the 3-layer affine chain into Weff (4x6) + beff (4).
// All math from SMEM after one coalesced staging pass -> latency-tolerant.
//   M1   = W2 @ W1                (100x6)
//   Weff = W3[0:4] @ M1           (4x6)
//   beff = b3 + W3[0:4] @ (W2@b1 + b2)
// ---------------------------------------------------------------------------
__global__ __launch_bounds__(256) void fold_weights_kernel(
    const float* __restrict__ W1, const float* __restrict__ b1,
    const float* __restrict__ W2, const float* __restrict__ b2,
    const float* __restrict__ W3, const float* __restrict__ b3) {
    __shared__ float sW2[100 * 50];   // 20 KB
    __shared__ float sW1[50 * 6];
    __shared__ float sW3[4 * 100];    // only rows 0..3 needed
    __shared__ float sb1[50];
    __shared__ float sb2[100];
    __shared__ float sM1[100 * 6];
    __shared__ float sw2b[100];

    const int t = threadIdx.x;

    // Stage weights (coalesced; W2 via float4: 5000 floats = 1250 float4)
    {
        const float4* W2v = reinterpret_cast<const float4*>(W2);
        float4* sW2v = reinterpret_cast<float4*>(sW2);
        for (int i = t; i < 1250; i += 256) sW2v[i] = W2v[i];
        for (int i = t; i < 300; i += 256) sW1[i] = W1[i];
        for (int i = t; i < 400; i += 256) sW3[i] = W3[i];  // rows 0..3 contiguous
        if (t < 50)  sb1[t] = b1[t];
        if (t < 100) sb2[t] = b2[t];
    }
    __syncthreads();

    // M1[j][i] = sum_c W2[j][c] * W1[c][i]   (600 entries, 50-FMA each)
    for (int idx = t; idx < 600; idx += 256) {
        const int j = idx / 6, i = idx % 6;
        float s = 0.f;
        #pragma unroll
        for (int c = 0; c < 50; ++c) s = fmaf(sW2[j * 50 + c], sW1[c * 6 + i], s);
        sM1[idx] = s;
    }
    // w2b[j] = sum_c W2[j][c] * b1[c]
    for (int j = t; j < 100; j += 256) {
        float s = 0.f;
        #pragma unroll
        for (int c = 0; c < 50; ++c) s = fmaf(sW2[j * 50 + c], sb1[c], s);
        sw2b[j] = s;
    }
    __syncthreads();

    // Weff[k][i] = sum_j W3[k][j] * M1[j][i]  (24 entries, 100-FMA each)
    if (t < 24) {
        const int k = t / 6, i = t % 6;
        float s = 0.f;
        #pragma unroll
        for (int j = 0; j < 100; ++j) s = fmaf(sW3[k * 100 + j], sM1[j * 6 + i], s);
        g_Weff[t] = s;
    }
    // beff[k] = b3[k] + sum_j W3[k][j] * (w2b[j] + b2[j])
    if (t >= 32 && t < 36) {
        const int k = t - 32;
        float s = b3[k];
        #pragma unroll
        for (int j = 0; j < 100; ++j) s = fmaf(sW3[k * 100 + j], sw2b[j] + sb2[j], s);
        g_beff[k] = s;
    }
}

// ---------------------------------------------------------------------------
// Main kernel: 4 outputs per thread, all float4 traffic.
// Per thread: 6 row float4 loads + 5 column float4 loads (X[0] unused!) +
// 1 float4 store. regs capped at 64 -> 4 CTAs/SM.
// ---------------------------------------------------------------------------
__global__ __launch_bounds__(256, 4) void barrier_main_kernel(
    const float* __restrict__ z, float* __restrict__ out, int nv /* = B/4 */) {
    const int t = blockIdx.x * blockDim.x + threadIdx.x;
    if (t >= nv) return;

    const float4* __restrict__ z4 = reinterpret_cast<const float4*>(z);

    // Folded affine parameters (uniform, L2/L1-resident)
    float W[24], bf[4];
    #pragma unroll
    for (int i = 0; i < 24; ++i) W[i] = g_Weff[i];
    #pragma unroll
    for (int i = 0; i < 4; ++i) bf[i] = g_beff[i];

    // Row data: z rows 4t..4t+3 = 24 contiguous floats
    float rf[24];
    #pragma unroll
    for (int k = 0; k < 6; ++k) {
        float4 v = z4[6 * t + k];
        rf[4 * k + 0] = v.x; rf[4 * k + 1] = v.y;
        rf[4 * k + 2] = v.z; rf[4 * k + 3] = v.w;
    }

    // Column data: X[i][4t..4t+3], i = 1..5 only (X[0] is dead)
    float xc[5][4];
    #pragma unroll
    for (int i = 0; i < 5; ++i) {
        float4 v = z4[(size_t)(i + 1) * nv + t];
        xc[i][0] = v.x; xc[i][1] = v.y; xc[i][2] = v.z; xc[i][3] = v.w;
    }

    // Constant d3u = d3 @ f (index 0 component is 0)
    const float d3u1 = TAU * ALPHA3;
    const float d3u2 = TAU * ALPHA1;
    const float d3u3 = 1.f - TAU * (ALPHA2 + ALPHA3);
    const float d3u4 = -TAU * ALPHA1;
    const float d3u5 = TAU * ALPHA2 - 1.f;
    // A = [-TAU, -TAU*ALPHA3], both negative -> ub=+inf, lb = max(h/A)
    const float invA0 = -1.f / TAU;
    const float invA1 = -1.f / (TAU * ALPHA3);

    float res[4];
    #pragma unroll
    for (int l = 0; l < 4; ++l) {
        // Folded affine "MLP": u0..u3
        float u0 = bf[0], u1 = bf[1], u2 = bf[2], u3 = bf[3];
        #pragma unroll
        for (int i = 0; i < 6; ++i) {
            const float zi = rf[6 * l + i];
            u0 = fmaf(W[i],      zi, u0);
            u1 = fmaf(W[6 + i],  zi, u1);
            u2 = fmaf(W[12 + i], zi, u2);
            u3 = fmaf(W[18 + i], zi, u3);
        }

        const float x1 = xc[0][l], x2 = xc[1][l], x3 = xc[2][l];
        const float x4 = xc[3][l], x5 = xc[4][l];

        const float fX2 = x1 - x3;
        const float fX3 = ALPHA3 * x1 + ALPHA1 * x2 - ALPHA2 * x3;
        const float fX4 = x3 - x5;
        const float fX5 = ALPHA3 * x3 + ALPHA1 * x4 - ALPHA2 * x5;

        const float eta1 = x2 + S_STAR - TAU * (x3 - x1);
        const float bb1  = fX2 - TAU * fX3 + u1 * eta1;

        const float eta2a = x4 + S_STAR - TAU * (x5 - x3);
        const float eta2b = d3u1 * x1 + d3u2 * x2 + d3u3 * x3 + d3u4 * x4 + d3u5 * x5;
        const float bb2   = d3u2 * fX2 + d3u3 * fX3 + d3u4 * fX4 + d3u5 * fX5
                          + u2 * eta2a + u3 * eta2b;

        const float lb = fmaxf(bb1 * invA0, bb2 * invA1);
        res[l] = fminf(fmaxf(2.f * u0, lb), 1e30f);
    }

    reinterpret_cast<float4*>(out)[t] =
        make_float4(res[0], res[1], res[2], res[3]);
}

// ---------------------------------------------------------------------------
// Inputs (metadata order): z, tilde_vh, W1, b1, W2, b2, W3, b3
// ---------------------------------------------------------------------------
extern "C" void kernel_launch(void* const* d_in, const int* in_sizes, int n_in,
                              void* d_out, int out_size) {
    const float* z  = (const float*)d_in[0];
    const float* W1 = (const float*)d_in[2];
    const float* b1 = (const float*)d_in[3];
    const float* W2 = (const float*)d_in[4];
    const float* b2 = (const float*)d_in[5];
    const float* W3 = (const float*)d_in[6];
    const float* b3 = (const float*)d_in[7];
    float* out = (float*)d_out;

    const int B  = in_sizes[0] / 6;   // 1048576
    const int nv = B / 4;             // 262144 float4 lanes

    fold_weights_kernel<<<1, 256>>>(W1, b1, W2, b2, W3, b3);

    const int threads = 256;
    const int blocks  = (nv + threads - 1) / threads;
    barrier_main_kernel<<<blocks, threads>>>(z, out, nv);
}

// round 3
// speedup vs baseline: 1.3915x; 1.0021x over previous
#include <cuda_runtime.h>

// Folded affine map: u[k] = Weff[k]·z_row + beff[k], k=0..3
__device__ float g_Weff[24];
__device__ float g_beff[4];

#define ALPHA1 1.2566f
#define ALPHA2 1.5f
#define ALPHA3 0.9f
#define S_STAR 20.0f
#define TAU    4.0f

// PDL primitives (inline PTX; sm_90+)
__device__ __forceinline__ void griddep_wait() {
    asm volatile("griddepcontrol.wait;" ::: "memory");
}
__device__ __forceinline__ void griddep_launch_dependents() {
    asm volatile("griddepcontrol.launch_dependents;");
}

// ---------------------------------------------------------------------------
// Prelude: fold the 3-layer affine chain.
//   T    = W3[0:4] @ W2        (4x50,  20K FMA)
//   Weff = T @ W1              (4x6)
//   beff = T @ b1 + W3[0:4] @ b2 + b3
// Single block; signals PDL dependents as soon as results are globally visible.
// ---------------------------------------------------------------------------
__global__ __launch_bounds__(256) void fold_weights_kernel(
    const float* __restrict__ W1, const float* __restrict__ b1,
    const float* __restrict__ W2, const float* __restrict__ b2,
    const float* __restrict__ W3, const float* __restrict__ b3) {
    __shared__ float sW2[100 * 50];   // 20 KB
    __shared__ float sW1[50 * 6];
    __shared__ float sW3[4 * 100];
    __shared__ float sb1[50];
    __shared__ float sb2[100];
    __shared__ float sT[4 * 50];

    const int t = threadIdx.x;

    // Stage weights (coalesced; W2 via float4)
    {
        const float4* W2v = reinterpret_cast<const float4*>(W2);
        float4* sW2v = reinterpret_cast<float4*>(sW2);
        for (int i = t; i < 1250; i += 256) sW2v[i] = W2v[i];
        for (int i = t; i < 300; i += 256) sW1[i] = W1[i];
        for (int i = t; i < 400; i += 256) sW3[i] = W3[i];  // rows 0..3
        if (t < 50)            sb1[t] = b1[t];
        if (t >= 64 && t < 164) sb2[t - 64] = b2[t - 64];
    }
    __syncthreads();

    // T[k][c] = sum_j W3[k][j] * W2[j][c]  (200 dots of 100, 2-way ILP)
    if (t < 200) {
        const int k = t / 50, c = t % 50;
        float s0 = 0.f, s1 = 0.f;
        #pragma unroll
        for (int j = 0; j < 100; j += 2) {
            s0 = fmaf(sW3[k * 100 + j],     sW2[j * 50 + c],       s0);
            s1 = fmaf(sW3[k * 100 + j + 1], sW2[(j + 1) * 50 + c], s1);
        }
        sT[t] = s0 + s1;
    }
    __syncthreads();

    // Weff[k][i] = sum_c T[k][c] * W1[c][i]
    if (t < 24) {
        const int k = t / 6, i = t % 6;
        float s = 0.f;
        #pragma unroll
        for (int c = 0; c < 50; ++c) s = fmaf(sT[k * 50 + c], sW1[c * 6 + i], s);
        g_Weff[t] = s;
    }
    // beff[k] = b3[k] + T[k]·b1 + W3[k]·b2
    if (t >= 32 && t < 36) {
        const int k = t - 32;
        float s = b3[k];
        #pragma unroll
        for (int c = 0; c < 50; ++c) s = fmaf(sT[k * 50 + c], sb1[c], s);
        #pragma unroll
        for (int j = 0; j < 100; ++j) s = fmaf(sW3[k * 100 + j], sb2[j], s);
        g_beff[k] = s;
    }
    // Make writes visible, then release the dependent (main) kernel's waiters.
    __threadfence();
    __syncthreads();
    griddep_launch_dependents();
}

// ---------------------------------------------------------------------------
// Main kernel (PDL secondary): issue ALL z loads first (independent of fold),
// then griddepcontrol.wait, then read folded weights and compute.
// 4 outputs/thread, all float4 traffic, 64 regs -> 4 CTAs/SM.
// ---------------------------------------------------------------------------
__global__ __launch_bounds__(256, 4) void barrier_main_kernel(
    const float* __restrict__ z, float* __restrict__ out, int nv /* = B/4 */) {
    const int t = blockIdx.x * blockDim.x + threadIdx.x;
    if (t >= nv) { griddep_wait(); return; }

    const float4* __restrict__ z4 = reinterpret_cast<const float4*>(z);

    // ---- Phase 1: z loads (overlap with fold kernel execution) ----
    // Row data: z rows 4t..4t+3 = 24 contiguous floats
    float rf[24];
    #pragma unroll
    for (int k = 0; k < 6; ++k) {
        float4 v = z4[6 * t + k];
        rf[4 * k + 0] = v.x; rf[4 * k + 1] = v.y;
        rf[4 * k + 2] = v.z; rf[4 * k + 3] = v.w;
    }
    // Column data: X[i][4t..4t+3], i = 1..5 (X[0] dead)
    float xc[5][4];
    #pragma unroll
    for (int i = 0; i < 5; ++i) {
        float4 v = z4[(size_t)(i + 1) * nv + t];
        xc[i][0] = v.x; xc[i][1] = v.y; xc[i][2] = v.z; xc[i][3] = v.w;
    }

    // ---- Phase 2: wait for fold results, then load them ----
    griddep_wait();

    float W[24], bf[4];
    #pragma unroll
    for (int i = 0; i < 24; ++i) W[i] = g_Weff[i];
    #pragma unroll
    for (int i = 0; i < 4; ++i) bf[i] = g_beff[i];

    // Constant d3u = d3 @ f (component 0 is 0)
    const float d3u1 = TAU * ALPHA3;
    const float d3u2 = TAU * ALPHA1;
    const float d3u3 = 1.f - TAU * (ALPHA2 + ALPHA3);
    const float d3u4 = -TAU * ALPHA1;
    const float d3u5 = TAU * ALPHA2 - 1.f;
    // A = [-TAU, -TAU*ALPHA3], both negative -> ub=+inf, lb = max(h/A)
    const float invA0 = -1.f / TAU;
    const float invA1 = -1.f / (TAU * ALPHA3);

    float res[4];
    #pragma unroll
    for (int l = 0; l < 4; ++l) {
        float u0 = bf[0], u1 = bf[1], u2 = bf[2], u3 = bf[3];
        #pragma unroll
        for (int i = 0; i < 6; ++i) {
            const float zi = rf[6 * l + i];
            u0 = fmaf(W[i],      zi, u0);
            u1 = fmaf(W[6 + i],  zi, u1);
            u2 = fmaf(W[12 + i], zi, u2);
            u3 = fmaf(W[18 + i], zi, u3);
        }

        const float x1 = xc[0][l], x2 = xc[1][l], x3 = xc[2][l];
        const float x4 = xc[3][l], x5 = xc[4][l];

        const float fX2 = x1 - x3;
        const float fX3 = ALPHA3 * x1 + ALPHA1 * x2 - ALPHA2 * x3;
        const float fX4 = x3 - x5;
        const float fX5 = ALPHA3 * x3 + ALPHA1 * x4 - ALPHA2 * x5;

        const float eta1 = x2 + S_STAR - TAU * (x3 - x1);
        const float bb1  = fX2 - TAU * fX3 + u1 * eta1;

        const float eta2a = x4 + S_STAR - TAU * (x5 - x3);
        const float eta2b = d3u1 * x1 + d3u2 * x2 + d3u3 * x3 + d3u4 * x4 + d3u5 * x5;
        const float bb2   = d3u2 * fX2 + d3u3 * fX3 + d3u4 * fX4 + d3u5 * fX5
                          + u2 * eta2a + u3 * eta2b;

        const float lb = fmaxf(bb1 * invA0, bb2 * invA1);
        res[l] = fminf(fmaxf(2.f * u0, lb), 1e30f);
    }

    reinterpret_cast<float4*>(out)[t] =
        make_float4(res[0], res[1], res[2], res[3]);
}

// ---------------------------------------------------------------------------
// Inputs (metadata order): z, tilde_vh, W1, b1, W2, b2, W3, b3
// ---------------------------------------------------------------------------
extern "C" void kernel_launch(void* const* d_in, const int* in_sizes, int n_in,
                              void* d_out, int out_size) {
    const float* z  = (const float*)d_in[0];
    const float* W1 = (const float*)d_in[2];
    const float* b1 = (const float*)d_in[3];
    const float* W2 = (const float*)d_in[4];
    const float* b2 = (const float*)d_in[5];
    const float* W3 = (const float*)d_in[6];
    const float* b3 = (const float*)d_in[7];
    float* out = (float*)d_out;

    const int B  = in_sizes[0] / 6;   // 1048576
    const int nv = B / 4;             // 262144 float4 lanes

    fold_weights_kernel<<<1, 256>>>(W1, b1, W2, b2, W3, b3);

    // Main kernel as PDL secondary: may begin (and stream z) while fold runs.
    const int threads = 256;
    const int blocks  = (nv + threads - 1) / threads;

    cudaLaunchConfig_t cfg = {};
    cfg.gridDim  = dim3(blocks);
    cfg.blockDim = dim3(threads);
    cfg.dynamicSmemBytes = 0;
    cfg.stream = 0;
    cudaLaunchAttribute attrs[1];
    attrs[0].id = cudaLaunchAttributeProgrammaticStreamSerialization;
    attrs[0].val.programmaticStreamSerializationAllowed = 1;
    cfg.attrs = attrs;
    cfg.numAttrs = 1;

    cudaLaunchKernelEx(&cfg, barrier_main_kernel, z, out, nv);
}

// round 4
// speedup vs baseline: 1.4156x; 1.0173x over previous
#include <cuda_runtime.h>
#include <cstdint>

// Folded affine map: u[k] = Weff[k]·z_row + beff[k], k=0..3
__device__ float g_Weff[24];
__device__ float g_beff[4];

#define ALPHA1 1.2566f
#define ALPHA2 1.5f
#define ALPHA3 0.9f
#define S_STAR 20.0f
#define TAU    4.0f

// ---- PDL primitives -------------------------------------------------------
__device__ __forceinline__ void griddep_wait() {
    asm volatile("griddepcontrol.wait;" ::: "memory");
}
__device__ __forceinline__ void griddep_launch_dependents() {
    asm volatile("griddepcontrol.launch_dependents;");
}

__device__ __forceinline__ uint32_t smem_u32(const void* p) {
    uint32_t a;
    asm("{ .reg .u64 t; cvta.to.shared.u64 t, %1; cvt.u32.u64 %0, t; }"
        : "=r"(a) : "l"(p));
    return a;
}

// ---------------------------------------------------------------------------
// Prelude: fold the 3-layer affine chain.
//   T    = W3[0:4] @ W2,  Weff = T @ W1,  beff = T@b1 + W3[0:4]@b2 + b3
// Triggers PDL dependents IMMEDIATELY so the main grid launches and streams z
// while this runs; dependents' griddepcontrol.wait covers completion.
// ---------------------------------------------------------------------------
__global__ __launch_bounds__(256) void fold_weights_kernel(
    const float* __restrict__ W1, const float* __restrict__ b1,
    const float* __restrict__ W2, const float* __restrict__ b2,
    const float* __restrict__ W3, const float* __restrict__ b3) {
    griddep_launch_dependents();   // release main grid NOW (max overlap)

    __shared__ float sW2[100 * 50];
    __shared__ float sW1[50 * 6];
    __shared__ float sW3[4 * 100];
    __shared__ float sb1[50];
    __shared__ float sb2[100];
    __shared__ float sT[4 * 50];

    const int t = threadIdx.x;
    {
        const float4* W2v = reinterpret_cast<const float4*>(W2);
        float4* sW2v = reinterpret_cast<float4*>(sW2);
        for (int i = t; i < 1250; i += 256) sW2v[i] = W2v[i];
        for (int i = t; i < 300; i += 256) sW1[i] = W1[i];
        for (int i = t; i < 400; i += 256) sW3[i] = W3[i];
        if (t < 50)             sb1[t] = b1[t];
        if (t >= 64 && t < 164) sb2[t - 64] = b2[t - 64];
    }
    __syncthreads();

    if (t < 200) {   // T[k][c] = W3[k]·W2[:,c]
        const int k = t / 50, c = t % 50;
        float s0 = 0.f, s1 = 0.f;
        #pragma unroll
        for (int j = 0; j < 100; j += 2) {
            s0 = fmaf(sW3[k * 100 + j],     sW2[j * 50 + c],       s0);
            s1 = fmaf(sW3[k * 100 + j + 1], sW2[(j + 1) * 50 + c], s1);
        }
        sT[t] = s0 + s1;
    }
    __syncthreads();

    if (t < 24) {    // Weff[k][i] = T[k]·W1[:,i]
        const int k = t / 6, i = t % 6;
        float s = 0.f;
        #pragma unroll
        for (int c = 0; c < 50; ++c) s = fmaf(sT[k * 50 + c], sW1[c * 6 + i], s);
        g_Weff[t] = s;
    }
    if (t >= 32 && t < 36) {  // beff
        const int k = t - 32;
        float s = b3[k];
        #pragma unroll
        for (int c = 0; c < 50; ++c) s = fmaf(sT[k * 50 + c], sb1[c], s);
        #pragma unroll
        for (int j = 0; j < 100; ++j) s = fmaf(sW3[k * 100 + j], sb2[j], s);
        g_beff[k] = s;
    }
}

// ---------------------------------------------------------------------------
// Main kernel: per-CTA bulk-async staging of 1024 outputs' worth of z
// (24KB contiguous rows + 5x4KB columns) into smem, mbarrier completion,
// then compute from smem. MLP lives in the async copy engine, not the RF.
// ---------------------------------------------------------------------------
__global__ __launch_bounds__(256) void barrier_main_kernel(
    const float* __restrict__ z, float* __restrict__ out, int B) {
    __shared__ __align__(128) float s_row[6 * 1024];   // 24 KB
    __shared__ __align__(128) float s_col[5 * 1024];   // 20 KB
    __shared__ __align__(8)  unsigned long long s_mbar;

    const int tid = threadIdx.x;
    const int j0  = blockIdx.x << 10;           // 1024 outputs per CTA
    const uint32_t mbar = smem_u32(&s_mbar);

    if (tid == 0) {
        asm volatile("mbarrier.init.shared.b64 [%0], %1;"
                     :: "r"(mbar), "r"(1) : "memory");
    }
    __syncthreads();

    if (tid == 0) {
        asm volatile("fence.proxy.async.shared::cta;" ::: "memory");
        asm volatile("mbarrier.arrive.expect_tx.shared.b64 _, [%0], %1;"
                     :: "r"(mbar), "r"(45056) : "memory");
        // rows: z[6*j0 .. 6*j0+6144)
        asm volatile(
            "cp.async.bulk.shared::cta.global.mbarrier::complete_tx::bytes "
            "[%0], [%1], %2, [%3];"
            :: "r"(smem_u32(s_row)), "l"(z + (size_t)6 * j0), "r"(24576),
               "r"(mbar) : "memory");
        // columns i=1..5: z[i*B + j0 .. +1024)
        #pragma unroll
        for (int i = 0; i < 5; ++i) {
            asm volatile(
                "cp.async.bulk.shared::cta.global.mbarrier::complete_tx::bytes "
                "[%0], [%1], %2, [%3];"
                :: "r"(smem_u32(s_col) + i * 4096),
                   "l"(z + (size_t)(i + 1) * B + j0), "r"(4096),
                   "r"(mbar) : "memory");
        }
    }

    // Wait for fold results (fold ran concurrently with the copies above)
    griddep_wait();
    float W[24], bf[4];
    #pragma unroll
    for (int i = 0; i < 24; ++i) W[i] = g_Weff[i];
    #pragma unroll
    for (int i = 0; i < 4; ++i) bf[i] = g_beff[i];

    // Wait for staged data (acquire: async writes visible after flip)
    {
        uint32_t done;
        asm volatile(
            "{\n\t.reg .pred p;\n\t"
            "mbarrier.try_wait.parity.acquire.cta.shared::cta.b64 p, [%1], %2;\n\t"
            "selp.b32 %0, 1, 0, p;\n\t}"
            : "=r"(done) : "r"(mbar), "r"(0) : "memory");
        if (!done) {
            asm volatile(
                "{\n\t.reg .pred P1;\n\t"
                "WL_%=:\n\t"
                "mbarrier.try_wait.parity.acquire.cta.shared::cta.b64 P1, [%0], %1, 0x989680;\n\t"
                "@P1 bra.uni WD_%=;\n\t"
                "bra.uni WL_%=;\n\t"
                "WD_%=:\n\t}"
                :: "r"(mbar), "r"(0) : "memory");
        }
    }

    // ---- Compute 4 outputs from smem ----
    const float4* row4 = reinterpret_cast<const float4*>(s_row);
    const float4* col4 = reinterpret_cast<const float4*>(s_col);

    float rf[24];
    #pragma unroll
    for (int k = 0; k < 6; ++k) {
        float4 v = row4[6 * tid + k];
        rf[4 * k + 0] = v.x; rf[4 * k + 1] = v.y;
        rf[4 * k + 2] = v.z; rf[4 * k + 3] = v.w;
    }
    float xc[5][4];
    #pragma unroll
    for (int i = 0; i < 5; ++i) {
        float4 v = col4[i * 256 + tid];
        xc[i][0] = v.x; xc[i][1] = v.y; xc[i][2] = v.z; xc[i][3] = v.w;
    }

    const float d3u1 = TAU * ALPHA3;
    const float d3u2 = TAU * ALPHA1;
    const float d3u3 = 1.f - TAU * (ALPHA2 + ALPHA3);
    const float d3u4 = -TAU * ALPHA1;
    const float d3u5 = TAU * ALPHA2 - 1.f;
    const float invA0 = -1.f / TAU;
    const float invA1 = -1.f / (TAU * ALPHA3);

    float res[4];
    #pragma unroll
    for (int l = 0; l < 4; ++l) {
        float u0 = bf[0], u1 = bf[1], u2 = bf[2], u3 = bf[3];
        #pragma unroll
        for (int i = 0; i < 6; ++i) {
            const float zi = rf[6 * l + i];
            u0 = fmaf(W[i],      zi, u0);
            u1 = fmaf(W[6 + i],  zi, u1);
            u2 = fmaf(W[12 + i], zi, u2);
            u3 = fmaf(W[18 + i], zi, u3);
        }

        const float x1 = xc[0][l], x2 = xc[1][l], x3 = xc[2][l];
        const float x4 = xc[3][l], x5 = xc[4][l];

        const float fX2 = x1 - x3;
        const float fX3 = ALPHA3 * x1 + ALPHA1 * x2 - ALPHA2 * x3;
        const float fX4 = x3 - x5;
        const float fX5 = ALPHA3 * x3 + ALPHA1 * x4 - ALPHA2 * x5;

        const float eta1 = x2 + S_STAR - TAU * (x3 - x1);
        const float bb1  = fX2 - TAU * fX3 + u1 * eta1;

        const float eta2a = x4 + S_STAR - TAU * (x5 - x3);
        const float eta2b = d3u1 * x1 + d3u2 * x2 + d3u3 * x3 + d3u4 * x4 + d3u5 * x5;
        const float bb2   = d3u2 * fX2 + d3u3 * fX3 + d3u4 * fX4 + d3u5 * fX5
                          + u2 * eta2a + u3 * eta2b;

        const float lb = fmaxf(bb1 * invA0, bb2 * invA1);
        res[l] = fminf(fmaxf(2.f * u0, lb), 1e30f);
    }

    reinterpret_cast<float4*>(out)[(size_t)(j0 >> 2) + tid] =
        make_float4(res[0], res[1], res[2], res[3]);
}

// ---------------------------------------------------------------------------
// Inputs (metadata order): z, tilde_vh, W1, b1, W2, b2, W3, b3
// ---------------------------------------------------------------------------
extern "C" void kernel_launch(void* const* d_in, const int* in_sizes, int n_in,
                              void* d_out, int out_size) {
    const float* z  = (const float*)d_in[0];
    const float* W1 = (const float*)d_in[2];
    const float* b1 = (const float*)d_in[3];
    const float* W2 = (const float*)d_in[4];
    const float* b2 = (const float*)d_in[5];
    const float* W3 = (const float*)d_in[6];
    const float* b3 = (const float*)d_in[7];
    float* out = (float*)d_out;

    const int B = in_sizes[0] / 6;          // 1048576
    const int blocks = B >> 10;             // 1024 outputs per CTA

    fold_weights_kernel<<<1, 256>>>(W1, b1, W2, b2, W3, b3);

    cudaLaunchConfig_t cfg = {};
    cfg.gridDim  = dim3(blocks);
    cfg.blockDim = dim3(256);
    cfg.dynamicSmemBytes = 0;
    cfg.stream = 0;
    cudaLaunchAttribute attrs[1];
    attrs[0].id = cudaLaunchAttributeProgrammaticStreamSerialization;
    attrs[0].val.programmaticStreamSerializationAllowed = 1;
    cfg.attrs = attrs;
    cfg.numAttrs = 1;

    cudaLaunchKernelEx(&cfg, barrier_main_kernel, z, out, B);
}

// round 5
// speedup vs baseline: 1.6069x; 1.1351x over previous
#include <cuda_runtime.h>
#include <cstdint>

// Folded affine map: u[k] = Weff[k]·z_row + beff[k], k=0..3
__device__ float g_Weff[24];
__device__ float g_beff[4];

#define ALPHA1 1.2566f
#define ALPHA2 1.5f
#define ALPHA3 0.9f
#define S_STAR 20.0f
#define TAU    4.0f

#define TILE        1024            // outputs per tile
#define ROW_BYTES   24576           // 6*TILE*4
#define COL_BYTES   4096            // TILE*4
#define STAGE_BYTES 45056           // ROW_BYTES + 5*COL_BYTES
#define NSTAGE      2

// ---- PDL / smem helpers ---------------------------------------------------
__device__ __forceinline__ void griddep_wait() {
    asm volatile("griddepcontrol.wait;" ::: "memory");
}
__device__ __forceinline__ void griddep_launch_dependents() {
    asm volatile("griddepcontrol.launch_dependents;");
}
__device__ __forceinline__ uint32_t smem_u32(const void* p) {
    uint32_t a;
    asm("{ .reg .u64 t; cvta.to.shared.u64 t, %1; cvt.u32.u64 %0, t; }"
        : "=r"(a) : "l"(p));
    return a;
}
__device__ __forceinline__ void mbar_wait(uint32_t mbar, uint32_t parity) {
    uint32_t done;
    asm volatile(
        "{\n\t.reg .pred p;\n\t"
        "mbarrier.try_wait.parity.acquire.cta.shared::cta.b64 p, [%1], %2;\n\t"
        "selp.b32 %0, 1, 0, p;\n\t}"
        : "=r"(done) : "r"(mbar), "r"(parity) : "memory");
    if (!done) {
        asm volatile(
            "{\n\t.reg .pred P1;\n\t"
            "WL_%=:\n\t"
            "mbarrier.try_wait.parity.acquire.cta.shared::cta.b64 P1, [%0], %1, 0x989680;\n\t"
            "@P1 bra.uni WD_%=;\n\t"
            "bra.uni WL_%=;\n\t"
            "WD_%=:\n\t}"
            :: "r"(mbar), "r"(parity) : "memory");
    }
}

// ---------------------------------------------------------------------------
// Prelude: fold the 3-layer affine chain. Early PDL trigger -> main grid
// launches and starts streaming z while this runs.
// ---------------------------------------------------------------------------
__global__ __launch_bounds__(256) void fold_weights_kernel(
    const float* __restrict__ W1, const float* __restrict__ b1,
    const float* __restrict__ W2, const float* __restrict__ b2,
    const float* __restrict__ W3, const float* __restrict__ b3) {
    griddep_launch_dependents();

    __shared__ float sW2[100 * 50];
    __shared__ float sW1[50 * 6];
    __shared__ float sW3[4 * 100];
    __shared__ float sb1[50];
    __shared__ float sb2[100];
    __shared__ float sT[4 * 50];

    const int t = threadIdx.x;
    {
        const float4* W2v = reinterpret_cast<const float4*>(W2);
        float4* sW2v = reinterpret_cast<float4*>(sW2);
        for (int i = t; i < 1250; i += 256) sW2v[i] = W2v[i];
        for (int i = t; i < 300; i += 256) sW1[i] = W1[i];
        for (int i = t; i < 400; i += 256) sW3[i] = W3[i];
        if (t < 50)             sb1[t] = b1[t];
        if (t >= 64 && t < 164) sb2[t - 64] = b2[t - 64];
    }
    __syncthreads();

    if (t < 200) {
        const int k = t / 50, c = t % 50;
        float s0 = 0.f, s1 = 0.f;
        #pragma unroll
        for (int j = 0; j < 100; j += 2) {
            s0 = fmaf(sW3[k * 100 + j],     sW2[j * 50 + c],       s0);
            s1 = fmaf(sW3[k * 100 + j + 1], sW2[(j + 1) * 50 + c], s1);
        }
        sT[t] = s0 + s1;
    }
    __syncthreads();

    if (t < 24) {
        const int k = t / 6, i = t % 6;
        float s = 0.f;
        #pragma unroll
        for (int c = 0; c < 50; ++c) s = fmaf(sT[k * 50 + c], sW1[c * 6 + i], s);
        g_Weff[t] = s;
    }
    if (t >= 32 && t < 36) {
        const int k = t - 32;
        float s = b3[k];
        #pragma unroll
        for (int c = 0; c < 50; ++c) s = fmaf(sT[k * 50 + c], sb1[c], s);
        #pragma unroll
        for (int j = 0; j < 100; ++j) s = fmaf(sW3[k * 100 + j], sb2[j], s);
        g_beff[k] = s;
    }
}

// ---------------------------------------------------------------------------
// Persistent main kernel: 296 CTAs (2/SM), each loops over tiles of 1024
// outputs with a 2-stage TMA pipeline (45KB/stage). Tile k+1 is issued
// before tile k is consumed -> 180KB in flight per SM, zero wave transitions.
// ---------------------------------------------------------------------------
__global__ __launch_bounds__(256) void barrier_main_kernel(
    const float* __restrict__ z, float* __restrict__ out,
    int B, int ntiles) {
    extern __shared__ __align__(128) char dynsmem[];
    __shared__ __align__(8) unsigned long long s_full[NSTAGE];

    const int tid = threadIdx.x;
    const uint32_t base = smem_u32(dynsmem);
    const uint32_t fullb = smem_u32(&s_full[0]);

    if (tid == 0) {
        #pragma unroll
        for (int s = 0; s < NSTAGE; ++s)
            asm volatile("mbarrier.init.shared.b64 [%0], %1;"
                         :: "r"(fullb + 8u * s), "r"(1) : "memory");
    }
    __syncthreads();
    if (tid == 0)
        asm volatile("fence.proxy.async.shared::cta;" ::: "memory");

    // Issue first tile's copies immediately (independent of fold kernel)
    auto issue_tile = [&](int t, int s) {
        const uint32_t mb = fullb + 8u * s;
        const uint32_t dst = base + (uint32_t)s * STAGE_BYTES;
        asm volatile("mbarrier.arrive.expect_tx.shared.b64 _, [%0], %1;"
                     :: "r"(mb), "r"(STAGE_BYTES) : "memory");
        asm volatile(
            "cp.async.bulk.shared::cta.global.mbarrier::complete_tx::bytes "
            "[%0], [%1], %2, [%3];"
            :: "r"(dst), "l"(z + (size_t)6 * TILE * t), "r"(ROW_BYTES),
               "r"(mb) : "memory");
        #pragma unroll
        for (int i = 0; i < 5; ++i) {
            asm volatile(
                "cp.async.bulk.shared::cta.global.mbarrier::complete_tx::bytes "
                "[%0], [%1], %2, [%3];"
                :: "r"(dst + ROW_BYTES + i * COL_BYTES),
                   "l"(z + (size_t)(i + 1) * B + (size_t)TILE * t),
                   "r"(COL_BYTES), "r"(mb) : "memory");
        }
    };

    if (tid == 0 && blockIdx.x < (unsigned)ntiles)
        issue_tile(blockIdx.x, 0);

    // Fold results (fold ran concurrently with the copy above)
    griddep_wait();
    float W[24], bf[4];
    #pragma unroll
    for (int i = 0; i < 24; ++i) W[i] = g_Weff[i];
    #pragma unroll
    for (int i = 0; i < 4; ++i) bf[i] = g_beff[i];

    const float d3u1 = TAU * ALPHA3;
    const float d3u2 = TAU * ALPHA1;
    const float d3u3 = 1.f - TAU * (ALPHA2 + ALPHA3);
    const float d3u4 = -TAU * ALPHA1;
    const float d3u5 = TAU * ALPHA2 - 1.f;
    const float invA0 = -1.f / TAU;
    const float invA1 = -1.f / (TAU * ALPHA3);

    int k = 0;
    for (int t = blockIdx.x; t < ntiles; t += gridDim.x, ++k) {
        const int s = k & 1;
        const int tn = t + gridDim.x;
        if (tid == 0 && tn < ntiles) issue_tile(tn, s ^ 1);

        mbar_wait(fullb + 8u * s, (k >> 1) & 1);

        const float4* row4 = reinterpret_cast<const float4*>(
            dynsmem + (size_t)s * STAGE_BYTES);
        const float4* col4 = reinterpret_cast<const float4*>(
            dynsmem + (size_t)s * STAGE_BYTES + ROW_BYTES);

        float rf[24];
        #pragma unroll
        for (int q = 0; q < 6; ++q) {
            float4 v = row4[6 * tid + q];
            rf[4 * q + 0] = v.x; rf[4 * q + 1] = v.y;
            rf[4 * q + 2] = v.z; rf[4 * q + 3] = v.w;
        }
        float xc[5][4];
        #pragma unroll
        for (int i = 0; i < 5; ++i) {
            float4 v = col4[i * 256 + tid];
            xc[i][0] = v.x; xc[i][1] = v.y; xc[i][2] = v.z; xc[i][3] = v.w;
        }

        float res[4];
        #pragma unroll
        for (int l = 0; l < 4; ++l) {
            float u0 = bf[0], u1 = bf[1], u2 = bf[2], u3 = bf[3];
            #pragma unroll
            for (int i = 0; i < 6; ++i) {
                const float zi = rf[6 * l + i];
                u0 = fmaf(W[i],      zi, u0);
                u1 = fmaf(W[6 + i],  zi, u1);
                u2 = fmaf(W[12 + i], zi, u2);
                u3 = fmaf(W[18 + i], zi, u3);
            }
            const float x1 = xc[0][l], x2 = xc[1][l], x3 = xc[2][l];
            const float x4 = xc[3][l], x5 = xc[4][l];

            const float fX2 = x1 - x3;
            const float fX3 = ALPHA3 * x1 + ALPHA1 * x2 - ALPHA2 * x3;
            const float fX4 = x3 - x5;
            const float fX5 = ALPHA3 * x3 + ALPHA1 * x4 - ALPHA2 * x5;

            const float eta1 = x2 + S_STAR - TAU * (x3 - x1);
            const float bb1  = fX2 - TAU * fX3 + u1 * eta1;

            const float eta2a = x4 + S_STAR - TAU * (x5 - x3);
            const float eta2b = d3u1 * x1 + d3u2 * x2 + d3u3 * x3
                              + d3u4 * x4 + d3u5 * x5;
            const float bb2   = d3u2 * fX2 + d3u3 * fX3 + d3u4 * fX4 + d3u5 * fX5
                              + u2 * eta2a + u3 * eta2b;

            const float lb = fmaxf(bb1 * invA0, bb2 * invA1);
            res[l] = fminf(fmaxf(2.f * u0, lb), 1e30f);
        }

        reinterpret_cast<float4*>(out)[(size_t)t * 256 + tid] =
            make_float4(res[0], res[1], res[2], res[3]);

        __syncthreads();   // stage s fully consumed before it is re-issued
    }
}

// ---------------------------------------------------------------------------
// Inputs (metadata order): z, tilde_vh, W1, b1, W2, b2, W3, b3
// ---------------------------------------------------------------------------
extern "C" void kernel_launch(void* const* d_in, const int* in_sizes, int n_in,
                              void* d_out, int out_size) {
    const float* z  = (const float*)d_in[0];
    const float* W1 = (const float*)d_in[2];
    const float* b1 = (const float*)d_in[3];
    const float* W2 = (const float*)d_in[4];
    const float* b2 = (const float*)d_in[5];
    const float* W3 = (const float*)d_in[6];
    const float* b3 = (const float*)d_in[7];
    float* out = (float*)d_out;

    const int B      = in_sizes[0] / 6;   // 1048576
    const int ntiles = B / TILE;          // 1024
    const int smem   = NSTAGE * STAGE_BYTES;  // 90112

    (void)cudaFuncSetAttribute(barrier_main_kernel,
                               cudaFuncAttributeMaxDynamicSharedMemorySize,
                               smem);

    fold_weights_kernel<<<1, 256>>>(W1, b1, W2, b2, W3, b3);

    int blocks = 296;                     // 2 CTAs/SM x 148 SMs
    if (blocks > ntiles) blocks = ntiles;

    cudaLaunchConfig_t cfg = {};
    cfg.gridDim  = dim3(blocks);
    cfg.blockDim = dim3(256);
    cfg.dynamicSmemBytes = smem;
    cfg.stream = 0;
    cudaLaunchAttribute attrs[1];
    attrs[0].id = cudaLaunchAttributeProgrammaticStreamSerialization;
    attrs[0].val.programmaticStreamSerializationAllowed = 1;
    cfg.attrs = attrs;
    cfg.numAttrs = 1;

    cudaLaunchKernelEx(&cfg, barrier_main_kernel, z, out, B, ntiles);
}